// round 7
// baseline (speedup 1.0000x reference)
#include <cuda_runtime.h>
#include <cuda_bf16.h>
#include <math.h>
#include <stdint.h>

#define B_ 64
#define L_ 2048
#define C_ 512
#define R_ 64

// Scratch (static device globals — no allocation APIs)
__device__ float g_hlow[B_ * C_ * R_];                          // (B, C, R) fp32
__device__ __align__(16) __nv_bfloat16 g_hattn[B_ * C_ * R_];   // (B, C, R) bf16
__device__ float g_kvpart[B_ * 8 * 64];

__device__ __forceinline__ void mma_tf32(float c[4],
                                         uint32_t a0, uint32_t a1, uint32_t a2, uint32_t a3,
                                         uint32_t b0, uint32_t b1) {
    asm volatile(
        "mma.sync.aligned.m16n8k8.row.col.f32.tf32.tf32.f32 "
        "{%0,%1,%2,%3}, {%4,%5,%6,%7}, {%8,%9}, {%0,%1,%2,%3};\n"
        : "+f"(c[0]), "+f"(c[1]), "+f"(c[2]), "+f"(c[3])
        : "r"(a0), "r"(a1), "r"(a2), "r"(a3), "r"(b0), "r"(b1));
}

__device__ __forceinline__ void mma_bf16(float c[4],
                                         uint32_t a0, uint32_t a1, uint32_t a2, uint32_t a3,
                                         uint32_t b0, uint32_t b1) {
    asm volatile(
        "mma.sync.aligned.m16n8k16.row.col.f32.bf16.bf16.f32 "
        "{%0,%1,%2,%3}, {%4,%5,%6,%7}, {%8,%9}, {%0,%1,%2,%3};\n"
        : "+f"(c[0]), "+f"(c[1]), "+f"(c[2]), "+f"(c[3])
        : "r"(a0), "r"(a1), "r"(a2), "r"(a3), "r"(b0), "r"(b1));
}

// ---------------------------------------------------------------------------
// Kernel 1 (tf32 mma + cp.async TRIPLE buffer, 1 barrier/chunk + fused kv):
// h_low[b,c,r] = sum_l x[b,l,c]*Wd[r,l] + bd[r]
// Then (fused, per CTA = one 64-token chunk): partial kv sums to g_kvpart.
// Grid (8, B), 256 thr. CTA tile 64c x 64r, K-chunks of 32.
// 8 warps = 4 output tiles (32c x 32r) x 2 k-halves.
// Dynamic smem: sA[3][32*72] | sB[3][64*40] | red[4][32*33]  (75264 B)
// Epilogue aliases: wA[64*65] | wB[64*65] | kv[64]
// ---------------------------------------------------------------------------
#define SA_STRIDE (32 * 72)
#define SB_STRIDE (64 * 40)
#define SB_BASE (3 * SA_STRIDE)
#define RED_BASE (SB_BASE + 3 * SB_STRIDE)

__global__ __launch_bounds__(256, 3) void k_hlow(const float* __restrict__ x,
                                                 const float* __restrict__ Wd,
                                                 const float* __restrict__ bd,
                                                 const float* __restrict__ Wk,
                                                 const float* __restrict__ Wv) {
    extern __shared__ float sm[];

    const int b = blockIdx.y;
    const int c0 = blockIdx.x * 64;
    const int tid = threadIdx.x;
    const int wid = tid >> 5;
    const int lane = tid & 31;
    const int g = lane >> 2;
    const int t4 = lane & 3;
    const int tile = wid & 3;
    const int kh = wid >> 2;  // k-half
    const int warpC = (tile & 1) * 32;
    const int warpR = (tile >> 1) * 32;

    const float* xb = x + (size_t)b * L_ * C_ + c0;

    float acc[2][4][4];
#pragma unroll
    for (int mt = 0; mt < 2; mt++)
#pragma unroll
        for (int nt = 0; nt < 4; nt++)
#pragma unroll
            for (int i = 0; i < 4; i++) acc[mt][nt][i] = 0.f;

#define ISSUE_CHUNK(l0, st)                                                       \
    {                                                                             \
        float* sA_ = sm + (st) * SA_STRIDE;                                       \
        float* sB_ = sm + SB_BASE + (st) * SB_STRIDE;                             \
        _Pragma("unroll") for (int i = 0; i < 2; i++) {                           \
            int t = tid + i * 256;                                                \
            int k = t >> 4, c4 = (t & 15) * 4;                                    \
            uint32_t dst =                                                        \
                (uint32_t)__cvta_generic_to_shared(&sA_[k * 72 + c4]);            \
            const float* src = &xb[(size_t)((l0) + k) * C_ + c4];                 \
            asm volatile("cp.async.cg.shared.global [%0], [%1], 16;" ::"r"(dst),  \
                         "l"(src));                                               \
        }                                                                         \
        _Pragma("unroll") for (int i = 0; i < 2; i++) {                           \
            int t = tid + i * 256;                                                \
            int r = t >> 3, k4 = (t & 7) * 4;                                     \
            uint32_t dst =                                                        \
                (uint32_t)__cvta_generic_to_shared(&sB_[r * 40 + k4]);            \
            const float* src = &Wd[r * L_ + (l0) + k4];                           \
            asm volatile("cp.async.cg.shared.global [%0], [%1], 16;" ::"r"(dst),  \
                         "l"(src));                                               \
        }                                                                         \
        asm volatile("cp.async.commit_group;");                                   \
    }

    ISSUE_CHUNK(0, 0);

    int stC = 0;   // compute stage
    int stI = 1;   // next issue stage
    for (int ch = 0; ch < 64; ch++) {
        if (ch < 63) {
            ISSUE_CHUNK((ch + 1) * 32, stI);
            stI = (stI == 2) ? 0 : stI + 1;
            asm volatile("cp.async.wait_group 1;");
        } else {
            asm volatile("cp.async.wait_group 0;");
        }
        __syncthreads();  // single barrier per chunk (safe with 3 stages)

        const float* a_ = sm + stC * SA_STRIDE;
        const float* b_ = sm + SB_BASE + stC * SB_STRIDE;
        stC = (stC == 2) ? 0 : stC + 1;

#pragma unroll
        for (int ks = 0; ks < 2; ks++) {
            int k0 = kh * 16 + ks * 8 + t4;
            uint32_t a[2][4];
#pragma unroll
            for (int mt = 0; mt < 2; mt++) {
                int cm = warpC + mt * 16 + g;
                a[mt][0] = __float_as_uint(a_[k0 * 72 + cm]);
                a[mt][1] = __float_as_uint(a_[k0 * 72 + cm + 8]);
                a[mt][2] = __float_as_uint(a_[(k0 + 4) * 72 + cm]);
                a[mt][3] = __float_as_uint(a_[(k0 + 4) * 72 + cm + 8]);
            }
#pragma unroll
            for (int nt = 0; nt < 4; nt++) {
                int rn = warpR + nt * 8 + g;
                uint32_t b0 = __float_as_uint(b_[rn * 40 + k0]);
                uint32_t b1 = __float_as_uint(b_[rn * 40 + k0 + 4]);
#pragma unroll
                for (int mt = 0; mt < 2; mt++)
                    mma_tf32(acc[mt][nt], a[mt][0], a[mt][1], a[mt][2], a[mt][3], b0, b1);
            }
        }
    }
#undef ISSUE_CHUNK

    // k-split reduction: kh=1 warps deposit, kh=0 warps add + write out.
    float* red = sm + RED_BASE;
    __syncthreads();  // all mma reads of stage buffers done
    if (kh == 1) {
#pragma unroll
        for (int mt = 0; mt < 2; mt++)
#pragma unroll
            for (int nt = 0; nt < 4; nt++)
#pragma unroll
                for (int i = 0; i < 4; i++)
                    red[tile * (32 * 33) + lane * 33 + mt * 16 + nt * 4 + i] = acc[mt][nt][i];
    }
    __syncthreads();
    if (kh == 0) {
#pragma unroll
        for (int mt = 0; mt < 2; mt++)
#pragma unroll
            for (int nt = 0; nt < 4; nt++)
#pragma unroll
                for (int i = 0; i < 4; i++)
                    acc[mt][nt][i] += red[tile * (32 * 33) + lane * 33 + mt * 16 + nt * 4 + i];

#pragma unroll
        for (int nt = 0; nt < 4; nt++) {
            int r = warpR + nt * 8 + t4 * 2;
            float b0v = bd[r], b1v = bd[r + 1];
#pragma unroll
            for (int mt = 0; mt < 2; mt++) {
                int c = c0 + warpC + mt * 16 + g;
                float2 v0 = {acc[mt][nt][0] + b0v, acc[mt][nt][1] + b1v};
                float2 v1 = {acc[mt][nt][2] + b0v, acc[mt][nt][3] + b1v};
                *(float2*)&g_hlow[((size_t)b * C_ + c) * R_ + r] = v0;
                *(float2*)&g_hlow[((size_t)b * C_ + c + 8) * R_ + r] = v1;
            }
        }
    }
    __syncthreads();  // g_hlow rows for this CTA's 64 tokens visible block-wide

    // ---- fused kv epilogue (former k_kv, chunk = blockIdx.x) ----
    float* wA = sm;
    float* wB = sm + 4160;
    float* kvs = sm + 8320;

    if (tid < 64) kvs[tid] = 0.f;
#pragma unroll
    for (int i = 0; i < 16; i++) {
        int idx = tid + i * 256;
        int o = idx >> 6, s = idx & 63;
        wA[s * 65 + o] = Wk[idx];
        wB[s * 65 + o] = Wv[idx];
    }
    __syncthreads();

    const int w = wid;
    float acc0 = 0.f, acc1 = 0.f;
#pragma unroll
    for (int it = 0; it < 8; it++) {
        int c = c0 + it * 8 + w;
        const float* hb = &g_hlow[((size_t)b * C_ + c) * R_];
        float h0 = hb[lane], h1 = hb[lane + 32];
        float k0 = 0.f, k1 = 0.f, v0 = 0.f, v1 = 0.f;
#pragma unroll
        for (int s = 0; s < 32; s++) {
            float ha = __shfl_sync(0xffffffffu, h0, s);
            float hc = __shfl_sync(0xffffffffu, h1, s);
            k0 += ha * wA[s * 65 + lane] + hc * wA[(s + 32) * 65 + lane];
            k1 += ha * wA[s * 65 + lane + 32] + hc * wA[(s + 32) * 65 + lane + 32];
            v0 += ha * wB[s * 65 + lane] + hc * wB[(s + 32) * 65 + lane];
            v1 += ha * wB[s * 65 + lane + 32] + hc * wB[(s + 32) * 65 + lane + 32];
        }
        float nk = k0 * k0 + k1 * k1;
#pragma unroll
        for (int off = 16; off > 0; off >>= 1) nk += __shfl_xor_sync(0xffffffffu, nk, off);
        float inv = 1.f / fmaxf(sqrtf(nk), 1e-12f);
        acc0 += k0 * inv * v0;
        acc1 += k1 * inv * v1;
    }
    atomicAdd(&kvs[lane], acc0);
    atomicAdd(&kvs[lane + 32], acc1);
    __syncthreads();
    if (tid < 64) g_kvpart[((size_t)b * 8 + blockIdx.x) * 64 + tid] = kvs[tid];
}

// ---------------------------------------------------------------------------
// Kernel 2b: Q, gate, h_attn (bf16 out). Grid (8, B), 256 thr.
// ---------------------------------------------------------------------------
__global__ __launch_bounds__(256) void k_qg(const float* __restrict__ Wq,
                                            const float* __restrict__ Wg,
                                            const float* __restrict__ bg) {
    __shared__ float wA[64 * 65];
    __shared__ float wB[64 * 65];
    __shared__ float kv[64];

    const int b = blockIdx.y;
    const int chunk = blockIdx.x;
    const int tid = threadIdx.x;
    const int lane = tid & 31;
    const int w = tid >> 5;

    if (tid < 64) {
        float s = 0.f;
#pragma unroll
        for (int j = 0; j < 8; j++) s += g_kvpart[((size_t)b * 8 + j) * 64 + tid];
        kv[tid] = s;
    }
#pragma unroll
    for (int i = 0; i < 16; i++) {
        int idx = tid + i * 256;
        int o = idx >> 6, s = idx & 63;
        wA[s * 65 + o] = Wq[idx];
        wB[s * 65 + o] = Wg[idx];
    }
    __syncthreads();

    float kv0t = kv[lane], kv1t = kv[lane + 32];
    float bg0 = bg[lane], bg1 = bg[lane + 32];

#pragma unroll
    for (int it = 0; it < 8; it++) {
        int c = chunk * 64 + it * 8 + w;
        const float* hb = &g_hlow[((size_t)b * C_ + c) * R_];
        float h0 = hb[lane], h1 = hb[lane + 32];
        float q0 = 0.f, q1 = 0.f, g0 = 0.f, g1 = 0.f;
#pragma unroll
        for (int s = 0; s < 32; s++) {
            float ha = __shfl_sync(0xffffffffu, h0, s);
            float hc = __shfl_sync(0xffffffffu, h1, s);
            q0 += ha * wA[s * 65 + lane] + hc * wA[(s + 32) * 65 + lane];
            q1 += ha * wA[s * 65 + lane + 32] + hc * wA[(s + 32) * 65 + lane + 32];
            g0 += ha * wB[s * 65 + lane] + hc * wB[(s + 32) * 65 + lane];
            g1 += ha * wB[s * 65 + lane + 32] + hc * wB[(s + 32) * 65 + lane + 32];
        }
        float nq = q0 * q0 + q1 * q1;
#pragma unroll
        for (int off = 16; off > 0; off >>= 1) nq += __shfl_xor_sync(0xffffffffu, nq, off);
        float inv = 1.f / fmaxf(sqrtf(nq), 1e-12f);
        float ga0 = 1.f / (1.f + expf(-(g0 + bg0)));
        float ga1 = 1.f / (1.f + expf(-(g1 + bg1)));
        __nv_bfloat16* ob = &g_hattn[((size_t)b * C_ + c) * R_];
        ob[lane]      = __float2bfloat16(q0 * inv * kv0t * ga0);
        ob[lane + 32] = __float2bfloat16(q1 * inv * kv1t * ga1);
    }
}

// ---------------------------------------------------------------------------
// Kernel 3 (bf16 mma m16n8k16): mixed[l,c] = sum_r Wu[l,r]*h_attn[c,r];
// out = LN_c(x + alpha*(mixed + bu)). Grid (64, B), 512 thr.
// (round-3 proven structure; B-fill via cp.async 16B)
// ---------------------------------------------------------------------------
__global__ __launch_bounds__(512, 2) void k_out(const float* __restrict__ x,
                                                const float* __restrict__ Wu,
                                                const float* __restrict__ bu,
                                                const float* __restrict__ gamma,
                                                const float* __restrict__ beta,
                                                const float* __restrict__ alpha_p,
                                                float* __restrict__ out) {
    extern __shared__ uint32_t sm3[];
    uint32_t* as_ = sm3;                 // [32][36] bf16x2 pairs of Wu
    uint32_t* bs_ = sm3 + 32 * 36;       // [512][36] bf16x2 pairs of h_attn
    float* outs = (float*)(sm3 + 32 * 36);  // alias over bs after mma: [32][516]

    const int b = blockIdx.y;
    const int l0 = blockIdx.x * 32;
    const int tid = threadIdx.x;
    const int wid = tid >> 5;
    const int lane = tid & 31;
    const int group = lane >> 2;
    const int t4 = lane & 3;
    const int lh = wid >> 3;
    const int cw = wid & 7;

    // fill B via cp.async: h_attn row c (64 bf16), 16B per op into bs[c][4q..4q+3]
    {
        const __nv_bfloat16* hb = &g_hattn[(size_t)b * C_ * R_];
        int q = tid & 7;
#pragma unroll
        for (int i = 0; i < 8; i++) {
            int c = (tid >> 3) + i * 64;
            uint32_t dst = (uint32_t)__cvta_generic_to_shared(&bs_[c * 36 + 4 * q]);
            const __nv_bfloat16* src = &hb[c * 64 + q * 8];
            asm volatile("cp.async.cg.shared.global [%0], [%1], 16;" ::"r"(dst), "l"(src));
        }
        asm volatile("cp.async.commit_group;");
    }
    // fill A: Wu[l0+l][2p..2p+1] -> as[l][p]
#pragma unroll
    for (int i = 0; i < 2; i++) {
        int idx = tid + i * 512;
        int l = idx >> 5, p = idx & 31;
        float2 w = *(const float2*)&Wu[(size_t)(l0 + l) * R_ + 2 * p];
        __nv_bfloat162 h2 = __float22bfloat162_rn(w);
        as_[l * 36 + p] = *(uint32_t*)&h2;
    }
    asm volatile("cp.async.wait_group 0;");
    __syncthreads();

    float acc[8][4];
#pragma unroll
    for (int nt = 0; nt < 8; nt++)
#pragma unroll
        for (int i = 0; i < 4; i++) acc[nt][i] = 0.f;

    const int rowA = lh * 16 + group;
#pragma unroll
    for (int ks = 0; ks < 4; ks++) {
        int pb = ks * 8 + t4;
        uint32_t a0 = as_[rowA * 36 + pb];
        uint32_t a1 = as_[(rowA + 8) * 36 + pb];
        uint32_t a2 = as_[rowA * 36 + pb + 4];
        uint32_t a3 = as_[(rowA + 8) * 36 + pb + 4];
#pragma unroll
        for (int nt = 0; nt < 8; nt++) {
            int cn = cw * 64 + nt * 8 + group;
            uint32_t b0 = bs_[cn * 36 + pb];
            uint32_t b1 = bs_[cn * 36 + pb + 4];
            mma_bf16(acc[nt], a0, a1, a2, a3, b0, b1);
        }
    }
    __syncthreads();  // all bs reads done; alias outs over bs

    // epilogue: mixed -> outs
#pragma unroll
    for (int nt = 0; nt < 8; nt++) {
        int c = cw * 64 + nt * 8 + t4 * 2;
        float2 v0 = {acc[nt][0], acc[nt][1]};
        float2 v1 = {acc[nt][2], acc[nt][3]};
        *(float2*)&outs[rowA * 516 + c] = v0;
        *(float2*)&outs[(rowA + 8) * 516 + c] = v1;
    }
    __syncthreads();

    // residual + LN over c; warp handles 2 rows
    const float alpha = *alpha_p;
#pragma unroll
    for (int rr = 0; rr < 2; rr++) {
        int li = wid * 2 + rr;
        float bul = bu[l0 + li];
        size_t xbase = ((size_t)b * L_ + l0 + li) * C_;
        float s = 0.f, ss = 0.f;
#pragma unroll
        for (int k = 0; k < 16; k++) {
            int c = lane + 32 * k;
            float m = outs[li * 516 + c];
            float v = x[xbase + c] + alpha * (m + bul);
            outs[li * 516 + c] = v;
            s += v;
            ss += v * v;
        }
#pragma unroll
        for (int off = 16; off > 0; off >>= 1) {
            s += __shfl_xor_sync(0xffffffffu, s, off);
            ss += __shfl_xor_sync(0xffffffffu, ss, off);
        }
        float mu = s * (1.f / 512.f);
        float var = ss * (1.f / 512.f) - mu * mu;
        float rstd = rsqrtf(var + 1e-5f);
#pragma unroll
        for (int k = 0; k < 16; k++) {
            int c = lane + 32 * k;
            float v = outs[li * 516 + c];
            out[xbase + c] = (v - mu) * rstd * gamma[c] + beta[c];
        }
    }
}

// ---------------------------------------------------------------------------
extern "C" void kernel_launch(void* const* d_in, const int* in_sizes, int n_in,
                              void* d_out, int out_size) {
    const float* x     = (const float*)d_in[0];
    const float* Wd    = (const float*)d_in[1];
    const float* bd    = (const float*)d_in[2];
    const float* Wq    = (const float*)d_in[3];
    const float* Wk    = (const float*)d_in[4];
    const float* Wv    = (const float*)d_in[5];
    const float* Wg    = (const float*)d_in[6];
    const float* bg    = (const float*)d_in[7];
    const float* Wu    = (const float*)d_in[8];
    const float* bu    = (const float*)d_in[9];
    const float* gamma = (const float*)d_in[10];
    const float* beta  = (const float*)d_in[11];
    const float* alpha = (const float*)d_in[12];
    float* out = (float*)d_out;

    static const int smem1 = (RED_BASE + 4 * 32 * 33) * 4;  // 75264 B
    static const int smem3 = (32 * 36 + 512 * 36) * 4;      // 78336 B
    static bool attr_set = false;
    if (!attr_set) {
        cudaFuncSetAttribute(k_hlow, cudaFuncAttributeMaxDynamicSharedMemorySize, smem1);
        cudaFuncSetAttribute(k_out, cudaFuncAttributeMaxDynamicSharedMemorySize, smem3);
        attr_set = true;
    }

    k_hlow<<<dim3(8, B_), 256, smem1>>>(x, Wd, bd, Wk, Wv);
    k_qg<<<dim3(8, B_), 256>>>(Wq, Wg, bg);
    k_out<<<dim3(64, B_), 512, smem3>>>(x, Wu, bu, gamma, beta, alpha, out);
}

// round 8
// speedup vs baseline: 1.1486x; 1.1486x over previous
#include <cuda_runtime.h>
#include <cuda_bf16.h>
#include <math.h>
#include <stdint.h>

#define B_ 64
#define L_ 2048
#define C_ 512
#define R_ 64

// Scratch (static device globals — no allocation APIs)
__device__ float g_hlow[B_ * C_ * R_];                          // (B, C, R) fp32
__device__ __align__(16) __nv_bfloat16 g_hattn[B_ * C_ * R_];   // (B, C, R) bf16
__device__ float g_kvpart[B_ * 8 * 64];

__device__ __forceinline__ void mma_tf32(float c[4],
                                         uint32_t a0, uint32_t a1, uint32_t a2, uint32_t a3,
                                         uint32_t b0, uint32_t b1) {
    asm volatile(
        "mma.sync.aligned.m16n8k8.row.col.f32.tf32.tf32.f32 "
        "{%0,%1,%2,%3}, {%4,%5,%6,%7}, {%8,%9}, {%0,%1,%2,%3};\n"
        : "+f"(c[0]), "+f"(c[1]), "+f"(c[2]), "+f"(c[3])
        : "r"(a0), "r"(a1), "r"(a2), "r"(a3), "r"(b0), "r"(b1));
}

__device__ __forceinline__ void mma_bf16(float c[4],
                                         uint32_t a0, uint32_t a1, uint32_t a2, uint32_t a3,
                                         uint32_t b0, uint32_t b1) {
    asm volatile(
        "mma.sync.aligned.m16n8k16.row.col.f32.bf16.bf16.f32 "
        "{%0,%1,%2,%3}, {%4,%5,%6,%7}, {%8,%9}, {%0,%1,%2,%3};\n"
        : "+f"(c[0]), "+f"(c[1]), "+f"(c[2]), "+f"(c[3])
        : "r"(a0), "r"(a1), "r"(a2), "r"(a3), "r"(b0), "r"(b1));
}

// ---------------------------------------------------------------------------
// Kernel 1 (round-6 proven): tf32 mma + cp.async double buffer + warp k-split.
// h_low[b,c,r] = sum_l x[b,l,c]*Wd[r,l] + bd[r]
// Grid (8, B), 256 thr. CTA tile 64c x 64r, K-chunks of 32.
// ---------------------------------------------------------------------------
__global__ __launch_bounds__(256, 4) void k_hlow(const float* __restrict__ x,
                                                 const float* __restrict__ Wd,
                                                 const float* __restrict__ bd) {
    __shared__ float sA[2][32 * 72];   // [k][c] pad 72
    __shared__ float sB[2][64 * 40];   // [r][k] pad 40
    __shared__ float red[4][32 * 33];  // k-split reduction

    const int b = blockIdx.y;
    const int c0 = blockIdx.x * 64;
    const int tid = threadIdx.x;
    const int wid = tid >> 5;
    const int lane = tid & 31;
    const int g = lane >> 2;
    const int t4 = lane & 3;
    const int tile = wid & 3;
    const int kh = wid >> 2;  // k-half
    const int warpC = (tile & 1) * 32;
    const int warpR = (tile >> 1) * 32;

    const float* xb = x + (size_t)b * L_ * C_ + c0;

    float acc[2][4][4];
#pragma unroll
    for (int mt = 0; mt < 2; mt++)
#pragma unroll
        for (int nt = 0; nt < 4; nt++)
#pragma unroll
            for (int i = 0; i < 4; i++) acc[mt][nt][i] = 0.f;

#define ISSUE_CHUNK(l0, st)                                                       \
    {                                                                             \
        _Pragma("unroll") for (int i = 0; i < 2; i++) {                           \
            int t = tid + i * 256;                                                \
            int k = t >> 4, c4 = (t & 15) * 4;                                    \
            uint32_t dst =                                                        \
                (uint32_t)__cvta_generic_to_shared(&sA[st][k * 72 + c4]);         \
            const float* src = &xb[(size_t)((l0) + k) * C_ + c4];                 \
            asm volatile("cp.async.cg.shared.global [%0], [%1], 16;" ::"r"(dst),  \
                         "l"(src));                                               \
        }                                                                         \
        _Pragma("unroll") for (int i = 0; i < 2; i++) {                           \
            int t = tid + i * 256;                                                \
            int r = t >> 3, k4 = (t & 7) * 4;                                     \
            uint32_t dst =                                                        \
                (uint32_t)__cvta_generic_to_shared(&sB[st][r * 40 + k4]);         \
            const float* src = &Wd[r * L_ + (l0) + k4];                           \
            asm volatile("cp.async.cg.shared.global [%0], [%1], 16;" ::"r"(dst),  \
                         "l"(src));                                               \
        }                                                                         \
        asm volatile("cp.async.commit_group;");                                   \
    }

    ISSUE_CHUNK(0, 0);

    for (int ch = 0; ch < 64; ch++) {
        if (ch < 63) {
            ISSUE_CHUNK((ch + 1) * 32, (ch + 1) & 1);
            asm volatile("cp.async.wait_group 1;");
        } else {
            asm volatile("cp.async.wait_group 0;");
        }
        __syncthreads();

        const float* a_ = sA[ch & 1];
        const float* b_ = sB[ch & 1];

#pragma unroll
        for (int ks = 0; ks < 2; ks++) {
            int k0 = kh * 16 + ks * 8 + t4;
            uint32_t a[2][4];
#pragma unroll
            for (int mt = 0; mt < 2; mt++) {
                int cm = warpC + mt * 16 + g;
                a[mt][0] = __float_as_uint(a_[k0 * 72 + cm]);
                a[mt][1] = __float_as_uint(a_[k0 * 72 + cm + 8]);
                a[mt][2] = __float_as_uint(a_[(k0 + 4) * 72 + cm]);
                a[mt][3] = __float_as_uint(a_[(k0 + 4) * 72 + cm + 8]);
            }
#pragma unroll
            for (int nt = 0; nt < 4; nt++) {
                int rn = warpR + nt * 8 + g;
                uint32_t b0 = __float_as_uint(b_[rn * 40 + k0]);
                uint32_t b1 = __float_as_uint(b_[rn * 40 + k0 + 4]);
#pragma unroll
                for (int mt = 0; mt < 2; mt++)
                    mma_tf32(acc[mt][nt], a[mt][0], a[mt][1], a[mt][2], a[mt][3], b0, b1);
            }
        }
        __syncthreads();
    }
#undef ISSUE_CHUNK

    // k-split reduction: kh=1 warps deposit, kh=0 warps add + write out.
    if (kh == 1) {
#pragma unroll
        for (int mt = 0; mt < 2; mt++)
#pragma unroll
            for (int nt = 0; nt < 4; nt++)
#pragma unroll
                for (int i = 0; i < 4; i++)
                    red[tile][lane * 33 + mt * 16 + nt * 4 + i] = acc[mt][nt][i];
    }
    __syncthreads();
    if (kh == 0) {
#pragma unroll
        for (int mt = 0; mt < 2; mt++)
#pragma unroll
            for (int nt = 0; nt < 4; nt++)
#pragma unroll
                for (int i = 0; i < 4; i++)
                    acc[mt][nt][i] += red[tile][lane * 33 + mt * 16 + nt * 4 + i];

#pragma unroll
        for (int nt = 0; nt < 4; nt++) {
            int r = warpR + nt * 8 + t4 * 2;
            float b0v = bd[r], b1v = bd[r + 1];
#pragma unroll
            for (int mt = 0; mt < 2; mt++) {
                int c = c0 + warpC + mt * 16 + g;
                float2 v0 = {acc[mt][nt][0] + b0v, acc[mt][nt][1] + b1v};
                float2 v1 = {acc[mt][nt][2] + b0v, acc[mt][nt][3] + b1v};
                *(float2*)&g_hlow[((size_t)b * C_ + c) * R_ + r] = v0;
                *(float2*)&g_hlow[((size_t)b * C_ + c + 8) * R_ + r] = v1;
            }
        }
    }
}

// ---------------------------------------------------------------------------
// Kernel 2a: partial kv sums. Grid (8, B), 256 thr; chunk = 64 tokens.
// ---------------------------------------------------------------------------
__global__ __launch_bounds__(256) void k_kv(const float* __restrict__ Wk,
                                            const float* __restrict__ Wv) {
    __shared__ float wA[64 * 65];
    __shared__ float wB[64 * 65];
    __shared__ float kv[64];

    const int b = blockIdx.y;
    const int chunk = blockIdx.x;
    const int tid = threadIdx.x;
    const int lane = tid & 31;
    const int w = tid >> 5;

    if (tid < 64) kv[tid] = 0.f;
#pragma unroll
    for (int i = 0; i < 16; i++) {
        int idx = tid + i * 256;
        int o = idx >> 6, s = idx & 63;
        wA[s * 65 + o] = Wk[idx];
        wB[s * 65 + o] = Wv[idx];
    }
    __syncthreads();

    float acc0 = 0.f, acc1 = 0.f;
#pragma unroll
    for (int it = 0; it < 8; it++) {
        int c = chunk * 64 + it * 8 + w;
        const float* hb = &g_hlow[((size_t)b * C_ + c) * R_];
        float h0 = hb[lane], h1 = hb[lane + 32];
        float k0 = 0.f, k1 = 0.f, v0 = 0.f, v1 = 0.f;
#pragma unroll
        for (int s = 0; s < 32; s++) {
            float ha = __shfl_sync(0xffffffffu, h0, s);
            float hc = __shfl_sync(0xffffffffu, h1, s);
            k0 += ha * wA[s * 65 + lane] + hc * wA[(s + 32) * 65 + lane];
            k1 += ha * wA[s * 65 + lane + 32] + hc * wA[(s + 32) * 65 + lane + 32];
            v0 += ha * wB[s * 65 + lane] + hc * wB[(s + 32) * 65 + lane];
            v1 += ha * wB[s * 65 + lane + 32] + hc * wB[(s + 32) * 65 + lane + 32];
        }
        float nk = k0 * k0 + k1 * k1;
#pragma unroll
        for (int off = 16; off > 0; off >>= 1) nk += __shfl_xor_sync(0xffffffffu, nk, off);
        float inv = 1.f / fmaxf(sqrtf(nk), 1e-12f);
        acc0 += k0 * inv * v0;
        acc1 += k1 * inv * v1;
    }
    atomicAdd(&kv[lane], acc0);
    atomicAdd(&kv[lane + 32], acc1);
    __syncthreads();
    if (tid < 64) g_kvpart[((size_t)b * 8 + chunk) * 64 + tid] = kv[tid];
}

// ---------------------------------------------------------------------------
// Kernel 2b: Q, gate, h_attn (bf16 out). Grid (8, B), 256 thr.
// ---------------------------------------------------------------------------
__global__ __launch_bounds__(256) void k_qg(const float* __restrict__ Wq,
                                            const float* __restrict__ Wg,
                                            const float* __restrict__ bg) {
    __shared__ float wA[64 * 65];
    __shared__ float wB[64 * 65];
    __shared__ float kv[64];

    const int b = blockIdx.y;
    const int chunk = blockIdx.x;
    const int tid = threadIdx.x;
    const int lane = tid & 31;
    const int w = tid >> 5;

    if (tid < 64) {
        float s = 0.f;
#pragma unroll
        for (int j = 0; j < 8; j++) s += g_kvpart[((size_t)b * 8 + j) * 64 + tid];
        kv[tid] = s;
    }
#pragma unroll
    for (int i = 0; i < 16; i++) {
        int idx = tid + i * 256;
        int o = idx >> 6, s = idx & 63;
        wA[s * 65 + o] = Wq[idx];
        wB[s * 65 + o] = Wg[idx];
    }
    __syncthreads();

    float kv0t = kv[lane], kv1t = kv[lane + 32];
    float bg0 = bg[lane], bg1 = bg[lane + 32];

#pragma unroll
    for (int it = 0; it < 8; it++) {
        int c = chunk * 64 + it * 8 + w;
        const float* hb = &g_hlow[((size_t)b * C_ + c) * R_];
        float h0 = hb[lane], h1 = hb[lane + 32];
        float q0 = 0.f, q1 = 0.f, g0 = 0.f, g1 = 0.f;
#pragma unroll
        for (int s = 0; s < 32; s++) {
            float ha = __shfl_sync(0xffffffffu, h0, s);
            float hc = __shfl_sync(0xffffffffu, h1, s);
            q0 += ha * wA[s * 65 + lane] + hc * wA[(s + 32) * 65 + lane];
            q1 += ha * wA[s * 65 + lane + 32] + hc * wA[(s + 32) * 65 + lane + 32];
            g0 += ha * wB[s * 65 + lane] + hc * wB[(s + 32) * 65 + lane];
            g1 += ha * wB[s * 65 + lane + 32] + hc * wB[(s + 32) * 65 + lane + 32];
        }
        float nq = q0 * q0 + q1 * q1;
#pragma unroll
        for (int off = 16; off > 0; off >>= 1) nq += __shfl_xor_sync(0xffffffffu, nq, off);
        float inv = 1.f / fmaxf(sqrtf(nq), 1e-12f);
        float ga0 = 1.f / (1.f + expf(-(g0 + bg0)));
        float ga1 = 1.f / (1.f + expf(-(g1 + bg1)));
        __nv_bfloat16* ob = &g_hattn[((size_t)b * C_ + c) * R_];
        ob[lane]      = __float2bfloat16(q0 * inv * kv0t * ga0);
        ob[lane + 32] = __float2bfloat16(q1 * inv * kv1t * ga1);
    }
}

// ---------------------------------------------------------------------------
// Kernel 3 (bf16 mma, occupancy-oriented): CTA tile 16l x 512c, 512 thr,
// 16 warps each m16 x n32. A (Wu) fragments loaded straight from global
// (L2-hot, 4KB slice shared by 64 batch-CTAs) — no smem A, fewer regs.
// Grid (128, B). smem = bs only (73.7KB) -> 3 CTAs/SM; regs <= 42.
// ---------------------------------------------------------------------------
__global__ __launch_bounds__(512, 3) void k_out(const float* __restrict__ x,
                                                const float* __restrict__ Wu,
                                                const float* __restrict__ bu,
                                                const float* __restrict__ gamma,
                                                const float* __restrict__ beta,
                                                const float* __restrict__ alpha_p,
                                                float* __restrict__ out) {
    extern __shared__ uint32_t sm3[];
    uint32_t* bs_ = sm3;                 // [512][36] bf16x2 pairs of h_attn
    float* outs = (float*)sm3;           // alias after mma: [16][516]

    const int b = blockIdx.y;
    const int l0 = blockIdx.x * 16;
    const int tid = threadIdx.x;
    const int wid = tid >> 5;
    const int lane = tid & 31;
    const int group = lane >> 2;
    const int t4 = lane & 3;

    // fill B via cp.async: h_attn row c (64 bf16), 16B per op into bs[c][4q..4q+3]
    {
        const __nv_bfloat16* hb = &g_hattn[(size_t)b * C_ * R_];
        int q = tid & 7;
#pragma unroll
        for (int i = 0; i < 8; i++) {
            int c = (tid >> 3) + i * 64;
            uint32_t dst = (uint32_t)__cvta_generic_to_shared(&bs_[c * 36 + 4 * q]);
            const __nv_bfloat16* src = &hb[c * 64 + q * 8];
            asm volatile("cp.async.cg.shared.global [%0], [%1], 16;" ::"r"(dst), "l"(src));
        }
        asm volatile("cp.async.commit_group;");
    }

    // A fragments direct from global (overlaps with cp.async fill)
    uint32_t af[4][4];
    {
        const float* w0 = &Wu[(size_t)(l0 + group) * R_];
        const float* w1 = &Wu[(size_t)(l0 + group + 8) * R_];
#pragma unroll
        for (int ks = 0; ks < 4; ks++) {
            int pb = ks * 8 + t4;
            float2 v00 = *(const float2*)&w0[2 * pb];
            float2 v10 = *(const float2*)&w1[2 * pb];
            float2 v01 = *(const float2*)&w0[2 * (pb + 4)];
            float2 v11 = *(const float2*)&w1[2 * (pb + 4)];
            __nv_bfloat162 h;
            h = __float22bfloat162_rn(v00); af[ks][0] = *(uint32_t*)&h;
            h = __float22bfloat162_rn(v10); af[ks][1] = *(uint32_t*)&h;
            h = __float22bfloat162_rn(v01); af[ks][2] = *(uint32_t*)&h;
            h = __float22bfloat162_rn(v11); af[ks][3] = *(uint32_t*)&h;
        }
    }
    asm volatile("cp.async.wait_group 0;");
    __syncthreads();

    float acc[4][4];
#pragma unroll
    for (int nt = 0; nt < 4; nt++)
#pragma unroll
        for (int i = 0; i < 4; i++) acc[nt][i] = 0.f;

#pragma unroll
    for (int ks = 0; ks < 4; ks++) {
        int pb = ks * 8 + t4;
#pragma unroll
        for (int nt = 0; nt < 4; nt++) {
            int cn = wid * 32 + nt * 8 + group;
            uint32_t b0 = bs_[cn * 36 + pb];
            uint32_t b1 = bs_[cn * 36 + pb + 4];
            mma_bf16(acc[nt], af[ks][0], af[ks][1], af[ks][2], af[ks][3], b0, b1);
        }
    }
    __syncthreads();  // all bs reads done; alias outs over bs

    // epilogue: mixed -> outs (rows group, group+8)
#pragma unroll
    for (int nt = 0; nt < 4; nt++) {
        int c = wid * 32 + nt * 8 + t4 * 2;
        float2 v0 = {acc[nt][0], acc[nt][1]};
        float2 v1 = {acc[nt][2], acc[nt][3]};
        *(float2*)&outs[group * 516 + c] = v0;
        *(float2*)&outs[(group + 8) * 516 + c] = v1;
    }
    __syncthreads();

    // residual + LN over c; warp wid handles row wid (16 warps, 16 rows)
    const float alpha = *alpha_p;
    {
        int li = wid;
        float bul = bu[l0 + li];
        size_t xbase = ((size_t)b * L_ + l0 + li) * C_;
        float s = 0.f, ss = 0.f;
#pragma unroll
        for (int k = 0; k < 16; k++) {
            int c = lane + 32 * k;
            float m = outs[li * 516 + c];
            float v = x[xbase + c] + alpha * (m + bul);
            outs[li * 516 + c] = v;
            s += v;
            ss += v * v;
        }
#pragma unroll
        for (int off = 16; off > 0; off >>= 1) {
            s += __shfl_xor_sync(0xffffffffu, s, off);
            ss += __shfl_xor_sync(0xffffffffu, ss, off);
        }
        float mu = s * (1.f / 512.f);
        float var = ss * (1.f / 512.f) - mu * mu;
        float rstd = rsqrtf(var + 1e-5f);
#pragma unroll
        for (int k = 0; k < 16; k++) {
            int c = lane + 32 * k;
            float v = outs[li * 516 + c];
            out[xbase + c] = (v - mu) * rstd * gamma[c] + beta[c];
        }
    }
}

// ---------------------------------------------------------------------------
extern "C" void kernel_launch(void* const* d_in, const int* in_sizes, int n_in,
                              void* d_out, int out_size) {
    const float* x     = (const float*)d_in[0];
    const float* Wd    = (const float*)d_in[1];
    const float* bd    = (const float*)d_in[2];
    const float* Wq    = (const float*)d_in[3];
    const float* Wk    = (const float*)d_in[4];
    const float* Wv    = (const float*)d_in[5];
    const float* Wg    = (const float*)d_in[6];
    const float* bg    = (const float*)d_in[7];
    const float* Wu    = (const float*)d_in[8];
    const float* bu    = (const float*)d_in[9];
    const float* gamma = (const float*)d_in[10];
    const float* beta  = (const float*)d_in[11];
    const float* alpha = (const float*)d_in[12];
    float* out = (float*)d_out;

    static const int smem3 = 512 * 36 * 4;  // 73728 B
    static bool attr_set = false;
    if (!attr_set) {
        cudaFuncSetAttribute(k_out, cudaFuncAttributeMaxDynamicSharedMemorySize, smem3);
        attr_set = true;
    }

    k_hlow<<<dim3(8, B_), 256>>>(x, Wd, bd);
    k_kv<<<dim3(8, B_), 256>>>(Wk, Wv);
    k_qg<<<dim3(8, B_), 256>>>(Wq, Wg, bg);
    k_out<<<dim3(128, B_), 512, smem3>>>(x, Wu, bu, gamma, beta, alpha, out);
}

// round 9
// speedup vs baseline: 1.5028x; 1.3084x over previous
#include <cuda_runtime.h>
#include <cuda_bf16.h>
#include <math.h>
#include <stdint.h>

#define B_ 64
#define L_ 2048
#define C_ 512
#define R_ 64

// Scratch (static device globals — no allocation APIs)
__device__ float g_hlow[B_ * C_ * R_];                          // (B, C, R) fp32
__device__ __align__(16) __nv_bfloat16 g_hattn[B_ * C_ * R_];   // (B, C, R) bf16
__device__ float g_kvpart[B_ * 8 * 64];

__device__ __forceinline__ void mma_tf32(float c[4],
                                         uint32_t a0, uint32_t a1, uint32_t a2, uint32_t a3,
                                         uint32_t b0, uint32_t b1) {
    asm volatile(
        "mma.sync.aligned.m16n8k8.row.col.f32.tf32.tf32.f32 "
        "{%0,%1,%2,%3}, {%4,%5,%6,%7}, {%8,%9}, {%0,%1,%2,%3};\n"
        : "+f"(c[0]), "+f"(c[1]), "+f"(c[2]), "+f"(c[3])
        : "r"(a0), "r"(a1), "r"(a2), "r"(a3), "r"(b0), "r"(b1));
}

__device__ __forceinline__ void mma_bf16(float c[4],
                                         uint32_t a0, uint32_t a1, uint32_t a2, uint32_t a3,
                                         uint32_t b0, uint32_t b1) {
    asm volatile(
        "mma.sync.aligned.m16n8k16.row.col.f32.bf16.bf16.f32 "
        "{%0,%1,%2,%3}, {%4,%5,%6,%7}, {%8,%9}, {%0,%1,%2,%3};\n"
        : "+f"(c[0]), "+f"(c[1]), "+f"(c[2]), "+f"(c[3])
        : "r"(a0), "r"(a1), "r"(a2), "r"(a3), "r"(b0), "r"(b1));
}

// ---------------------------------------------------------------------------
// Kernel 1 (round-6 proven, FROZEN): tf32 mma + cp.async double buffer +
// warp k-split. h_low[b,c,r] = sum_l x[b,l,c]*Wd[r,l] + bd[r]
// Grid (8, B), 256 thr. CTA tile 64c x 64r, K-chunks of 32.
// ---------------------------------------------------------------------------
__global__ __launch_bounds__(256, 4) void k_hlow(const float* __restrict__ x,
                                                 const float* __restrict__ Wd,
                                                 const float* __restrict__ bd) {
    __shared__ float sA[2][32 * 72];   // [k][c] pad 72
    __shared__ float sB[2][64 * 40];   // [r][k] pad 40
    __shared__ float red[4][32 * 33];  // k-split reduction

    const int b = blockIdx.y;
    const int c0 = blockIdx.x * 64;
    const int tid = threadIdx.x;
    const int wid = tid >> 5;
    const int lane = tid & 31;
    const int g = lane >> 2;
    const int t4 = lane & 3;
    const int tile = wid & 3;
    const int kh = wid >> 2;  // k-half
    const int warpC = (tile & 1) * 32;
    const int warpR = (tile >> 1) * 32;

    const float* xb = x + (size_t)b * L_ * C_ + c0;

    float acc[2][4][4];
#pragma unroll
    for (int mt = 0; mt < 2; mt++)
#pragma unroll
        for (int nt = 0; nt < 4; nt++)
#pragma unroll
            for (int i = 0; i < 4; i++) acc[mt][nt][i] = 0.f;

#define ISSUE_CHUNK(l0, st)                                                       \
    {                                                                             \
        _Pragma("unroll") for (int i = 0; i < 2; i++) {                           \
            int t = tid + i * 256;                                                \
            int k = t >> 4, c4 = (t & 15) * 4;                                    \
            uint32_t dst =                                                        \
                (uint32_t)__cvta_generic_to_shared(&sA[st][k * 72 + c4]);         \
            const float* src = &xb[(size_t)((l0) + k) * C_ + c4];                 \
            asm volatile("cp.async.cg.shared.global [%0], [%1], 16;" ::"r"(dst),  \
                         "l"(src));                                               \
        }                                                                         \
        _Pragma("unroll") for (int i = 0; i < 2; i++) {                           \
            int t = tid + i * 256;                                                \
            int r = t >> 3, k4 = (t & 7) * 4;                                     \
            uint32_t dst =                                                        \
                (uint32_t)__cvta_generic_to_shared(&sB[st][r * 40 + k4]);         \
            const float* src = &Wd[r * L_ + (l0) + k4];                           \
            asm volatile("cp.async.cg.shared.global [%0], [%1], 16;" ::"r"(dst),  \
                         "l"(src));                                               \
        }                                                                         \
        asm volatile("cp.async.commit_group;");                                   \
    }

    ISSUE_CHUNK(0, 0);

    for (int ch = 0; ch < 64; ch++) {
        if (ch < 63) {
            ISSUE_CHUNK((ch + 1) * 32, (ch + 1) & 1);
            asm volatile("cp.async.wait_group 1;");
        } else {
            asm volatile("cp.async.wait_group 0;");
        }
        __syncthreads();

        const float* a_ = sA[ch & 1];
        const float* b_ = sB[ch & 1];

#pragma unroll
        for (int ks = 0; ks < 2; ks++) {
            int k0 = kh * 16 + ks * 8 + t4;
            uint32_t a[2][4];
#pragma unroll
            for (int mt = 0; mt < 2; mt++) {
                int cm = warpC + mt * 16 + g;
                a[mt][0] = __float_as_uint(a_[k0 * 72 + cm]);
                a[mt][1] = __float_as_uint(a_[k0 * 72 + cm + 8]);
                a[mt][2] = __float_as_uint(a_[(k0 + 4) * 72 + cm]);
                a[mt][3] = __float_as_uint(a_[(k0 + 4) * 72 + cm + 8]);
            }
#pragma unroll
            for (int nt = 0; nt < 4; nt++) {
                int rn = warpR + nt * 8 + g;
                uint32_t b0 = __float_as_uint(b_[rn * 40 + k0]);
                uint32_t b1 = __float_as_uint(b_[rn * 40 + k0 + 4]);
#pragma unroll
                for (int mt = 0; mt < 2; mt++)
                    mma_tf32(acc[mt][nt], a[mt][0], a[mt][1], a[mt][2], a[mt][3], b0, b1);
            }
        }
        __syncthreads();
    }
#undef ISSUE_CHUNK

    // k-split reduction: kh=1 warps deposit, kh=0 warps add + write out.
    if (kh == 1) {
#pragma unroll
        for (int mt = 0; mt < 2; mt++)
#pragma unroll
            for (int nt = 0; nt < 4; nt++)
#pragma unroll
                for (int i = 0; i < 4; i++)
                    red[tile][lane * 33 + mt * 16 + nt * 4 + i] = acc[mt][nt][i];
    }
    __syncthreads();
    if (kh == 0) {
#pragma unroll
        for (int mt = 0; mt < 2; mt++)
#pragma unroll
            for (int nt = 0; nt < 4; nt++)
#pragma unroll
                for (int i = 0; i < 4; i++)
                    acc[mt][nt][i] += red[tile][lane * 33 + mt * 16 + nt * 4 + i];

#pragma unroll
        for (int nt = 0; nt < 4; nt++) {
            int r = warpR + nt * 8 + t4 * 2;
            float b0v = bd[r], b1v = bd[r + 1];
#pragma unroll
            for (int mt = 0; mt < 2; mt++) {
                int c = c0 + warpC + mt * 16 + g;
                float2 v0 = {acc[mt][nt][0] + b0v, acc[mt][nt][1] + b1v};
                float2 v1 = {acc[mt][nt][2] + b0v, acc[mt][nt][3] + b1v};
                *(float2*)&g_hlow[((size_t)b * C_ + c) * R_ + r] = v0;
                *(float2*)&g_hlow[((size_t)b * C_ + c + 8) * R_ + r] = v1;
            }
        }
    }
}

// ---------------------------------------------------------------------------
// Kernel 2a: partial kv sums. Grid (8, B), 256 thr; chunk = 64 tokens.
// ---------------------------------------------------------------------------
__global__ __launch_bounds__(256) void k_kv(const float* __restrict__ Wk,
                                            const float* __restrict__ Wv) {
    __shared__ float wA[64 * 65];
    __shared__ float wB[64 * 65];
    __shared__ float kv[64];

    const int b = blockIdx.y;
    const int chunk = blockIdx.x;
    const int tid = threadIdx.x;
    const int lane = tid & 31;
    const int w = tid >> 5;

    if (tid < 64) kv[tid] = 0.f;
#pragma unroll
    for (int i = 0; i < 16; i++) {
        int idx = tid + i * 256;
        int o = idx >> 6, s = idx & 63;
        wA[s * 65 + o] = Wk[idx];
        wB[s * 65 + o] = Wv[idx];
    }
    __syncthreads();

    float acc0 = 0.f, acc1 = 0.f;
#pragma unroll
    for (int it = 0; it < 8; it++) {
        int c = chunk * 64 + it * 8 + w;
        const float* hb = &g_hlow[((size_t)b * C_ + c) * R_];
        float h0 = hb[lane], h1 = hb[lane + 32];
        float k0 = 0.f, k1 = 0.f, v0 = 0.f, v1 = 0.f;
#pragma unroll
        for (int s = 0; s < 32; s++) {
            float ha = __shfl_sync(0xffffffffu, h0, s);
            float hc = __shfl_sync(0xffffffffu, h1, s);
            k0 += ha * wA[s * 65 + lane] + hc * wA[(s + 32) * 65 + lane];
            k1 += ha * wA[s * 65 + lane + 32] + hc * wA[(s + 32) * 65 + lane + 32];
            v0 += ha * wB[s * 65 + lane] + hc * wB[(s + 32) * 65 + lane];
            v1 += ha * wB[s * 65 + lane + 32] + hc * wB[(s + 32) * 65 + lane + 32];
        }
        float nk = k0 * k0 + k1 * k1;
#pragma unroll
        for (int off = 16; off > 0; off >>= 1) nk += __shfl_xor_sync(0xffffffffu, nk, off);
        float inv = 1.f / fmaxf(sqrtf(nk), 1e-12f);
        acc0 += k0 * inv * v0;
        acc1 += k1 * inv * v1;
    }
    atomicAdd(&kv[lane], acc0);
    atomicAdd(&kv[lane + 32], acc1);
    __syncthreads();
    if (tid < 64) g_kvpart[((size_t)b * 8 + chunk) * 64 + tid] = kv[tid];
}

// ---------------------------------------------------------------------------
// Kernel 2b: Q, gate, h_attn (bf16 out). Grid (8, B), 256 thr.
// ---------------------------------------------------------------------------
__global__ __launch_bounds__(256) void k_qg(const float* __restrict__ Wq,
                                            const float* __restrict__ Wg,
                                            const float* __restrict__ bg) {
    __shared__ float wA[64 * 65];
    __shared__ float wB[64 * 65];
    __shared__ float kv[64];

    const int b = blockIdx.y;
    const int chunk = blockIdx.x;
    const int tid = threadIdx.x;
    const int lane = tid & 31;
    const int w = tid >> 5;

    if (tid < 64) {
        float s = 0.f;
#pragma unroll
        for (int j = 0; j < 8; j++) s += g_kvpart[((size_t)b * 8 + j) * 64 + tid];
        kv[tid] = s;
    }
#pragma unroll
    for (int i = 0; i < 16; i++) {
        int idx = tid + i * 256;
        int o = idx >> 6, s = idx & 63;
        wA[s * 65 + o] = Wq[idx];
        wB[s * 65 + o] = Wg[idx];
    }
    __syncthreads();

    float kv0t = kv[lane], kv1t = kv[lane + 32];
    float bg0 = bg[lane], bg1 = bg[lane + 32];

#pragma unroll
    for (int it = 0; it < 8; it++) {
        int c = chunk * 64 + it * 8 + w;
        const float* hb = &g_hlow[((size_t)b * C_ + c) * R_];
        float h0 = hb[lane], h1 = hb[lane + 32];
        float q0 = 0.f, q1 = 0.f, g0 = 0.f, g1 = 0.f;
#pragma unroll
        for (int s = 0; s < 32; s++) {
            float ha = __shfl_sync(0xffffffffu, h0, s);
            float hc = __shfl_sync(0xffffffffu, h1, s);
            q0 += ha * wA[s * 65 + lane] + hc * wA[(s + 32) * 65 + lane];
            q1 += ha * wA[s * 65 + lane + 32] + hc * wA[(s + 32) * 65 + lane + 32];
            g0 += ha * wB[s * 65 + lane] + hc * wB[(s + 32) * 65 + lane];
            g1 += ha * wB[s * 65 + lane + 32] + hc * wB[(s + 32) * 65 + lane + 32];
        }
        float nq = q0 * q0 + q1 * q1;
#pragma unroll
        for (int off = 16; off > 0; off >>= 1) nq += __shfl_xor_sync(0xffffffffu, nq, off);
        float inv = 1.f / fmaxf(sqrtf(nq), 1e-12f);
        float ga0 = 1.f / (1.f + expf(-(g0 + bg0)));
        float ga1 = 1.f / (1.f + expf(-(g1 + bg1)));
        __nv_bfloat16* ob = &g_hattn[((size_t)b * C_ + c) * R_];
        ob[lane]      = __float2bfloat16(q0 * inv * kv0t * ga0);
        ob[lane + 32] = __float2bfloat16(q1 * inv * kv1t * ga1);
    }
}

// ---------------------------------------------------------------------------
// Kernel 3 (bf16 mma, round-6 shape + slim epilogue):
// mixed staged through smem ONCE as bf16x2 (32KB); LN keeps pre-LN v in regs.
// Grid (64, B), 512 thr. CTA tile 32l x 512c.
// ---------------------------------------------------------------------------
__global__ __launch_bounds__(512, 2) void k_out(const float* __restrict__ x,
                                                const float* __restrict__ Wu,
                                                const float* __restrict__ bu,
                                                const float* __restrict__ gamma,
                                                const float* __restrict__ beta,
                                                const float* __restrict__ alpha_p,
                                                float* __restrict__ out) {
    extern __shared__ uint32_t sm3[];
    uint32_t* as_ = sm3;             // [32][36] bf16x2 pairs of Wu
    uint32_t* bs_ = sm3 + 32 * 36;   // [512][36] bf16x2 pairs of h_attn
    uint32_t* mx = sm3 + 32 * 36;    // alias after mma: [32][260] bf16x2 mixed

    const int b = blockIdx.y;
    const int l0 = blockIdx.x * 32;
    const int tid = threadIdx.x;
    const int wid = tid >> 5;
    const int lane = tid & 31;
    const int group = lane >> 2;
    const int t4 = lane & 3;
    const int lh = wid >> 3;
    const int cw = wid & 7;

    // fill B via cp.async: h_attn row c (64 bf16), 16B per op
    {
        const __nv_bfloat16* hb = &g_hattn[(size_t)b * C_ * R_];
        int q = tid & 7;
#pragma unroll
        for (int i = 0; i < 8; i++) {
            int c = (tid >> 3) + i * 64;
            uint32_t dst = (uint32_t)__cvta_generic_to_shared(&bs_[c * 36 + 4 * q]);
            const __nv_bfloat16* src = &hb[c * 64 + q * 8];
            asm volatile("cp.async.cg.shared.global [%0], [%1], 16;" ::"r"(dst), "l"(src));
        }
        asm volatile("cp.async.commit_group;");
    }
    // fill A: Wu[l0+l][2p..2p+1] -> as[l][p]
#pragma unroll
    for (int i = 0; i < 2; i++) {
        int idx = tid + i * 512;
        int l = idx >> 5, p = idx & 31;
        float2 w = *(const float2*)&Wu[(size_t)(l0 + l) * R_ + 2 * p];
        __nv_bfloat162 h2 = __float22bfloat162_rn(w);
        as_[l * 36 + p] = *(uint32_t*)&h2;
    }
    asm volatile("cp.async.wait_group 0;");
    __syncthreads();

    float acc[8][4];
#pragma unroll
    for (int nt = 0; nt < 8; nt++)
#pragma unroll
        for (int i = 0; i < 4; i++) acc[nt][i] = 0.f;

    const int rowA = lh * 16 + group;
#pragma unroll
    for (int ks = 0; ks < 4; ks++) {
        int pb = ks * 8 + t4;
        uint32_t a0 = as_[rowA * 36 + pb];
        uint32_t a1 = as_[(rowA + 8) * 36 + pb];
        uint32_t a2 = as_[rowA * 36 + pb + 4];
        uint32_t a3 = as_[(rowA + 8) * 36 + pb + 4];
#pragma unroll
        for (int nt = 0; nt < 8; nt++) {
            int cn = cw * 64 + nt * 8 + group;
            uint32_t b0 = bs_[cn * 36 + pb];
            uint32_t b1 = bs_[cn * 36 + pb + 4];
            mma_bf16(acc[nt], a0, a1, a2, a3, b0, b1);
        }
    }
    __syncthreads();  // all bs reads done; alias mx over bs

    // epilogue: pack mixed to bf16x2, single smem write
#pragma unroll
    for (int nt = 0; nt < 8; nt++) {
        int ch = cw * 32 + nt * 4 + t4;  // uint32 index = c/2
        __nv_bfloat162 p0 = __float22bfloat162_rn(make_float2(acc[nt][0], acc[nt][1]));
        __nv_bfloat162 p1 = __float22bfloat162_rn(make_float2(acc[nt][2], acc[nt][3]));
        mx[rowA * 260 + ch] = *(uint32_t*)&p0;
        mx[(rowA + 8) * 260 + ch] = *(uint32_t*)&p1;
    }
    __syncthreads();

    // residual + LN over c; warp handles 2 rows, v kept in registers
    const float alpha = *alpha_p;
#pragma unroll
    for (int rr = 0; rr < 2; rr++) {
        int li = wid * 2 + rr;
        float bul = bu[l0 + li];
        size_t xbase = ((size_t)b * L_ + l0 + li) * C_;
        float vx[16];
        float s = 0.f, ss = 0.f;
#pragma unroll
        for (int k = 0; k < 8; k++) {
            int j = lane + 32 * k;  // uint32 index; covers c = 2j, 2j+1
            uint32_t pm = mx[li * 260 + j];
            float2 m = __bfloat1622float2(*(__nv_bfloat162*)&pm);
            float2 xv = *(const float2*)&x[xbase + 2 * j];
            float v0 = xv.x + alpha * (m.x + bul);
            float v1 = xv.y + alpha * (m.y + bul);
            vx[2 * k] = v0;
            vx[2 * k + 1] = v1;
            s += v0 + v1;
            ss += v0 * v0 + v1 * v1;
        }
#pragma unroll
        for (int off = 16; off > 0; off >>= 1) {
            s += __shfl_xor_sync(0xffffffffu, s, off);
            ss += __shfl_xor_sync(0xffffffffu, ss, off);
        }
        float mu = s * (1.f / 512.f);
        float var = ss * (1.f / 512.f) - mu * mu;
        float rstd = rsqrtf(var + 1e-5f);
#pragma unroll
        for (int k = 0; k < 8; k++) {
            int j = lane + 32 * k;
            float2 gm = *(const float2*)&gamma[2 * j];
            float2 bt = *(const float2*)&beta[2 * j];
            float2 o;
            o.x = (vx[2 * k] - mu) * rstd * gm.x + bt.x;
            o.y = (vx[2 * k + 1] - mu) * rstd * gm.y + bt.y;
            *(float2*)&out[xbase + 2 * j] = o;
        }
    }
}

// ---------------------------------------------------------------------------
extern "C" void kernel_launch(void* const* d_in, const int* in_sizes, int n_in,
                              void* d_out, int out_size) {
    const float* x     = (const float*)d_in[0];
    const float* Wd    = (const float*)d_in[1];
    const float* bd    = (const float*)d_in[2];
    const float* Wq    = (const float*)d_in[3];
    const float* Wk    = (const float*)d_in[4];
    const float* Wv    = (const float*)d_in[5];
    const float* Wg    = (const float*)d_in[6];
    const float* bg    = (const float*)d_in[7];
    const float* Wu    = (const float*)d_in[8];
    const float* bu    = (const float*)d_in[9];
    const float* gamma = (const float*)d_in[10];
    const float* beta  = (const float*)d_in[11];
    const float* alpha = (const float*)d_in[12];
    float* out = (float*)d_out;

    static const int smem3 = (32 * 36 + 512 * 36) * 4;  // 78336 B
    static bool attr_set = false;
    if (!attr_set) {
        cudaFuncSetAttribute(k_out, cudaFuncAttributeMaxDynamicSharedMemorySize, smem3);
        attr_set = true;
    }

    k_hlow<<<dim3(8, B_), 256>>>(x, Wd, bd);
    k_kv<<<dim3(8, B_), 256>>>(Wk, Wv);
    k_qg<<<dim3(8, B_), 256>>>(Wq, Wg, bg);
    k_out<<<dim3(64, B_), 512, smem3>>>(x, Wu, bu, gamma, beta, alpha, out);
}

// round 10
// speedup vs baseline: 1.5131x; 1.0069x over previous
#include <cuda_runtime.h>
#include <cuda_bf16.h>
#include <math.h>
#include <stdint.h>

#define B_ 64
#define L_ 2048
#define C_ 512
#define R_ 64

// Scratch (static device globals — no allocation APIs)
__device__ float g_hlow[B_ * C_ * R_];                          // (B, C, R) k-half 0 (+bd)
__device__ float g_hlow2[B_ * C_ * R_];                         // (B, C, R) k-half 1
__device__ __align__(16) __nv_bfloat16 g_hattn[B_ * C_ * R_];   // (B, C, R) bf16
__device__ float g_kvpart[B_ * 8 * 64];

__device__ __forceinline__ void mma_tf32(float c[4],
                                         uint32_t a0, uint32_t a1, uint32_t a2, uint32_t a3,
                                         uint32_t b0, uint32_t b1) {
    asm volatile(
        "mma.sync.aligned.m16n8k8.row.col.f32.tf32.tf32.f32 "
        "{%0,%1,%2,%3}, {%4,%5,%6,%7}, {%8,%9}, {%0,%1,%2,%3};\n"
        : "+f"(c[0]), "+f"(c[1]), "+f"(c[2]), "+f"(c[3])
        : "r"(a0), "r"(a1), "r"(a2), "r"(a3), "r"(b0), "r"(b1));
}

__device__ __forceinline__ void mma_bf16(float c[4],
                                         uint32_t a0, uint32_t a1, uint32_t a2, uint32_t a3,
                                         uint32_t b0, uint32_t b1) {
    asm volatile(
        "mma.sync.aligned.m16n8k16.row.col.f32.bf16.bf16.f32 "
        "{%0,%1,%2,%3}, {%4,%5,%6,%7}, {%8,%9}, {%0,%1,%2,%3};\n"
        : "+f"(c[0]), "+f"(c[1]), "+f"(c[2]), "+f"(c[3])
        : "r"(a0), "r"(a1), "r"(a2), "r"(a3), "r"(b0), "r"(b1));
}

// ---------------------------------------------------------------------------
// Kernel 1 (round-6 inner loop, K split across blockIdx.z):
// partial h_low over L-half [z*1024, (z+1)*1024). Grid (8, B, 2), 256 thr.
// CTA tile 64c x 64r, K-chunks of 32 (32 chunks per CTA).
// ---------------------------------------------------------------------------
__global__ __launch_bounds__(256, 4) void k_hlow(const float* __restrict__ x,
                                                 const float* __restrict__ Wd,
                                                 const float* __restrict__ bd) {
    __shared__ float sA[2][32 * 72];   // [k][c] pad 72
    __shared__ float sB[2][64 * 40];   // [r][k] pad 40
    __shared__ float red[4][32 * 33];  // k-split reduction

    const int b = blockIdx.y;
    const int c0 = blockIdx.x * 64;
    const int z = blockIdx.z;
    const int lbase = z * 1024;
    const int tid = threadIdx.x;
    const int wid = tid >> 5;
    const int lane = tid & 31;
    const int g = lane >> 2;
    const int t4 = lane & 3;
    const int tile = wid & 3;
    const int kh = wid >> 2;  // k-half within CTA
    const int warpC = (tile & 1) * 32;
    const int warpR = (tile >> 1) * 32;

    const float* xb = x + (size_t)b * L_ * C_ + (size_t)lbase * C_ + c0;
    const float* wdb = Wd;  // indexed with lbase below

    float acc[2][4][4];
#pragma unroll
    for (int mt = 0; mt < 2; mt++)
#pragma unroll
        for (int nt = 0; nt < 4; nt++)
#pragma unroll
            for (int i = 0; i < 4; i++) acc[mt][nt][i] = 0.f;

#define ISSUE_CHUNK(l0, st)                                                       \
    {                                                                             \
        _Pragma("unroll") for (int i = 0; i < 2; i++) {                           \
            int t = tid + i * 256;                                                \
            int k = t >> 4, c4 = (t & 15) * 4;                                    \
            uint32_t dst =                                                        \
                (uint32_t)__cvta_generic_to_shared(&sA[st][k * 72 + c4]);         \
            const float* src = &xb[(size_t)((l0) + k) * C_ + c4];                 \
            asm volatile("cp.async.cg.shared.global [%0], [%1], 16;" ::"r"(dst),  \
                         "l"(src));                                               \
        }                                                                         \
        _Pragma("unroll") for (int i = 0; i < 2; i++) {                           \
            int t = tid + i * 256;                                                \
            int r = t >> 3, k4 = (t & 7) * 4;                                     \
            uint32_t dst =                                                        \
                (uint32_t)__cvta_generic_to_shared(&sB[st][r * 40 + k4]);         \
            const float* src = &wdb[r * L_ + lbase + (l0) + k4];                  \
            asm volatile("cp.async.cg.shared.global [%0], [%1], 16;" ::"r"(dst),  \
                         "l"(src));                                               \
        }                                                                         \
        asm volatile("cp.async.commit_group;");                                   \
    }

    ISSUE_CHUNK(0, 0);

    for (int ch = 0; ch < 32; ch++) {
        if (ch < 31) {
            ISSUE_CHUNK((ch + 1) * 32, (ch + 1) & 1);
            asm volatile("cp.async.wait_group 1;");
        } else {
            asm volatile("cp.async.wait_group 0;");
        }
        __syncthreads();

        const float* a_ = sA[ch & 1];
        const float* b_ = sB[ch & 1];

#pragma unroll
        for (int ks = 0; ks < 2; ks++) {
            int k0 = kh * 16 + ks * 8 + t4;
            uint32_t a[2][4];
#pragma unroll
            for (int mt = 0; mt < 2; mt++) {
                int cm = warpC + mt * 16 + g;
                a[mt][0] = __float_as_uint(a_[k0 * 72 + cm]);
                a[mt][1] = __float_as_uint(a_[k0 * 72 + cm + 8]);
                a[mt][2] = __float_as_uint(a_[(k0 + 4) * 72 + cm]);
                a[mt][3] = __float_as_uint(a_[(k0 + 4) * 72 + cm + 8]);
            }
#pragma unroll
            for (int nt = 0; nt < 4; nt++) {
                int rn = warpR + nt * 8 + g;
                uint32_t b0 = __float_as_uint(b_[rn * 40 + k0]);
                uint32_t b1 = __float_as_uint(b_[rn * 40 + k0 + 4]);
#pragma unroll
                for (int mt = 0; mt < 2; mt++)
                    mma_tf32(acc[mt][nt], a[mt][0], a[mt][1], a[mt][2], a[mt][3], b0, b1);
            }
        }
        __syncthreads();
    }
#undef ISSUE_CHUNK

    // k-split reduction: kh=1 warps deposit, kh=0 warps add + write out.
    if (kh == 1) {
#pragma unroll
        for (int mt = 0; mt < 2; mt++)
#pragma unroll
            for (int nt = 0; nt < 4; nt++)
#pragma unroll
                for (int i = 0; i < 4; i++)
                    red[tile][lane * 33 + mt * 16 + nt * 4 + i] = acc[mt][nt][i];
    }
    __syncthreads();
    if (kh == 0) {
#pragma unroll
        for (int mt = 0; mt < 2; mt++)
#pragma unroll
            for (int nt = 0; nt < 4; nt++)
#pragma unroll
                for (int i = 0; i < 4; i++)
                    acc[mt][nt][i] += red[tile][lane * 33 + mt * 16 + nt * 4 + i];

        float* outp = (z == 0) ? g_hlow : g_hlow2;
#pragma unroll
        for (int nt = 0; nt < 4; nt++) {
            int r = warpR + nt * 8 + t4 * 2;
            float b0v = (z == 0) ? bd[r] : 0.f;
            float b1v = (z == 0) ? bd[r + 1] : 0.f;
#pragma unroll
            for (int mt = 0; mt < 2; mt++) {
                int c = c0 + warpC + mt * 16 + g;
                float2 v0 = {acc[mt][nt][0] + b0v, acc[mt][nt][1] + b1v};
                float2 v1 = {acc[mt][nt][2] + b0v, acc[mt][nt][3] + b1v};
                *(float2*)&outp[((size_t)b * C_ + c) * R_ + r] = v0;
                *(float2*)&outp[((size_t)b * C_ + c + 8) * R_ + r] = v1;
            }
        }
    }
}

// ---------------------------------------------------------------------------
// Kernel 2a: partial kv sums. Grid (8, B), 256 thr; chunk = 64 tokens.
// h_low = g_hlow + g_hlow2 (k-split partials).
// ---------------------------------------------------------------------------
__global__ __launch_bounds__(256) void k_kv(const float* __restrict__ Wk,
                                            const float* __restrict__ Wv) {
    __shared__ float wA[64 * 65];
    __shared__ float wB[64 * 65];
    __shared__ float kv[64];

    const int b = blockIdx.y;
    const int chunk = blockIdx.x;
    const int tid = threadIdx.x;
    const int lane = tid & 31;
    const int w = tid >> 5;

    if (tid < 64) kv[tid] = 0.f;
#pragma unroll
    for (int i = 0; i < 16; i++) {
        int idx = tid + i * 256;
        int o = idx >> 6, s = idx & 63;
        wA[s * 65 + o] = Wk[idx];
        wB[s * 65 + o] = Wv[idx];
    }
    __syncthreads();

    float acc0 = 0.f, acc1 = 0.f;
#pragma unroll
    for (int it = 0; it < 8; it++) {
        int c = chunk * 64 + it * 8 + w;
        size_t off = ((size_t)b * C_ + c) * R_;
        float h0 = g_hlow[off + lane] + g_hlow2[off + lane];
        float h1 = g_hlow[off + lane + 32] + g_hlow2[off + lane + 32];
        float k0 = 0.f, k1 = 0.f, v0 = 0.f, v1 = 0.f;
#pragma unroll
        for (int s = 0; s < 32; s++) {
            float ha = __shfl_sync(0xffffffffu, h0, s);
            float hc = __shfl_sync(0xffffffffu, h1, s);
            k0 += ha * wA[s * 65 + lane] + hc * wA[(s + 32) * 65 + lane];
            k1 += ha * wA[s * 65 + lane + 32] + hc * wA[(s + 32) * 65 + lane + 32];
            v0 += ha * wB[s * 65 + lane] + hc * wB[(s + 32) * 65 + lane];
            v1 += ha * wB[s * 65 + lane + 32] + hc * wB[(s + 32) * 65 + lane + 32];
        }
        float nk = k0 * k0 + k1 * k1;
#pragma unroll
        for (int off2 = 16; off2 > 0; off2 >>= 1) nk += __shfl_xor_sync(0xffffffffu, nk, off2);
        float inv = 1.f / fmaxf(sqrtf(nk), 1e-12f);
        acc0 += k0 * inv * v0;
        acc1 += k1 * inv * v1;
    }
    atomicAdd(&kv[lane], acc0);
    atomicAdd(&kv[lane + 32], acc1);
    __syncthreads();
    if (tid < 64) g_kvpart[((size_t)b * 8 + chunk) * 64 + tid] = kv[tid];
}

// ---------------------------------------------------------------------------
// Kernel 2b: Q, gate, h_attn (bf16 out). Grid (8, B), 256 thr.
// ---------------------------------------------------------------------------
__global__ __launch_bounds__(256) void k_qg(const float* __restrict__ Wq,
                                            const float* __restrict__ Wg,
                                            const float* __restrict__ bg) {
    __shared__ float wA[64 * 65];
    __shared__ float wB[64 * 65];
    __shared__ float kv[64];

    const int b = blockIdx.y;
    const int chunk = blockIdx.x;
    const int tid = threadIdx.x;
    const int lane = tid & 31;
    const int w = tid >> 5;

    if (tid < 64) {
        float s = 0.f;
#pragma unroll
        for (int j = 0; j < 8; j++) s += g_kvpart[((size_t)b * 8 + j) * 64 + tid];
        kv[tid] = s;
    }
#pragma unroll
    for (int i = 0; i < 16; i++) {
        int idx = tid + i * 256;
        int o = idx >> 6, s = idx & 63;
        wA[s * 65 + o] = Wq[idx];
        wB[s * 65 + o] = Wg[idx];
    }
    __syncthreads();

    float kv0t = kv[lane], kv1t = kv[lane + 32];
    float bg0 = bg[lane], bg1 = bg[lane + 32];

#pragma unroll
    for (int it = 0; it < 8; it++) {
        int c = chunk * 64 + it * 8 + w;
        size_t off = ((size_t)b * C_ + c) * R_;
        float h0 = g_hlow[off + lane] + g_hlow2[off + lane];
        float h1 = g_hlow[off + lane + 32] + g_hlow2[off + lane + 32];
        float q0 = 0.f, q1 = 0.f, g0 = 0.f, g1 = 0.f;
#pragma unroll
        for (int s = 0; s < 32; s++) {
            float ha = __shfl_sync(0xffffffffu, h0, s);
            float hc = __shfl_sync(0xffffffffu, h1, s);
            q0 += ha * wA[s * 65 + lane] + hc * wA[(s + 32) * 65 + lane];
            q1 += ha * wA[s * 65 + lane + 32] + hc * wA[(s + 32) * 65 + lane + 32];
            g0 += ha * wB[s * 65 + lane] + hc * wB[(s + 32) * 65 + lane];
            g1 += ha * wB[s * 65 + lane + 32] + hc * wB[(s + 32) * 65 + lane + 32];
        }
        float nq = q0 * q0 + q1 * q1;
#pragma unroll
        for (int off2 = 16; off2 > 0; off2 >>= 1) nq += __shfl_xor_sync(0xffffffffu, nq, off2);
        float inv = 1.f / fmaxf(sqrtf(nq), 1e-12f);
        float ga0 = 1.f / (1.f + expf(-(g0 + bg0)));
        float ga1 = 1.f / (1.f + expf(-(g1 + bg1)));
        __nv_bfloat16* ob = &g_hattn[((size_t)b * C_ + c) * R_];
        ob[lane]      = __float2bfloat16(q0 * inv * kv0t * ga0);
        ob[lane + 32] = __float2bfloat16(q1 * inv * kv1t * ga1);
    }
}

// ---------------------------------------------------------------------------
// Kernel 3 (round-9 proven, FROZEN): bf16 mma + bf16 single-pass mixed staging.
// Grid (64, B), 512 thr. CTA tile 32l x 512c.
// ---------------------------------------------------------------------------
__global__ __launch_bounds__(512, 2) void k_out(const float* __restrict__ x,
                                                const float* __restrict__ Wu,
                                                const float* __restrict__ bu,
                                                const float* __restrict__ gamma,
                                                const float* __restrict__ beta,
                                                const float* __restrict__ alpha_p,
                                                float* __restrict__ out) {
    extern __shared__ uint32_t sm3[];
    uint32_t* as_ = sm3;             // [32][36] bf16x2 pairs of Wu
    uint32_t* bs_ = sm3 + 32 * 36;   // [512][36] bf16x2 pairs of h_attn
    uint32_t* mx = sm3 + 32 * 36;    // alias after mma: [32][260] bf16x2 mixed

    const int b = blockIdx.y;
    const int l0 = blockIdx.x * 32;
    const int tid = threadIdx.x;
    const int wid = tid >> 5;
    const int lane = tid & 31;
    const int group = lane >> 2;
    const int t4 = lane & 3;
    const int lh = wid >> 3;
    const int cw = wid & 7;

    // fill B via cp.async: h_attn row c (64 bf16), 16B per op
    {
        const __nv_bfloat16* hb = &g_hattn[(size_t)b * C_ * R_];
        int q = tid & 7;
#pragma unroll
        for (int i = 0; i < 8; i++) {
            int c = (tid >> 3) + i * 64;
            uint32_t dst = (uint32_t)__cvta_generic_to_shared(&bs_[c * 36 + 4 * q]);
            const __nv_bfloat16* src = &hb[c * 64 + q * 8];
            asm volatile("cp.async.cg.shared.global [%0], [%1], 16;" ::"r"(dst), "l"(src));
        }
        asm volatile("cp.async.commit_group;");
    }
    // fill A: Wu[l0+l][2p..2p+1] -> as[l][p]
#pragma unroll
    for (int i = 0; i < 2; i++) {
        int idx = tid + i * 512;
        int l = idx >> 5, p = idx & 31;
        float2 w = *(const float2*)&Wu[(size_t)(l0 + l) * R_ + 2 * p];
        __nv_bfloat162 h2 = __float22bfloat162_rn(w);
        as_[l * 36 + p] = *(uint32_t*)&h2;
    }
    asm volatile("cp.async.wait_group 0;");
    __syncthreads();

    float acc[8][4];
#pragma unroll
    for (int nt = 0; nt < 8; nt++)
#pragma unroll
        for (int i = 0; i < 4; i++) acc[nt][i] = 0.f;

    const int rowA = lh * 16 + group;
#pragma unroll
    for (int ks = 0; ks < 4; ks++) {
        int pb = ks * 8 + t4;
        uint32_t a0 = as_[rowA * 36 + pb];
        uint32_t a1 = as_[(rowA + 8) * 36 + pb];
        uint32_t a2 = as_[rowA * 36 + pb + 4];
        uint32_t a3 = as_[(rowA + 8) * 36 + pb + 4];
#pragma unroll
        for (int nt = 0; nt < 8; nt++) {
            int cn = cw * 64 + nt * 8 + group;
            uint32_t b0 = bs_[cn * 36 + pb];
            uint32_t b1 = bs_[cn * 36 + pb + 4];
            mma_bf16(acc[nt], a0, a1, a2, a3, b0, b1);
        }
    }
    __syncthreads();  // all bs reads done; alias mx over bs

    // epilogue: pack mixed to bf16x2, single smem write
#pragma unroll
    for (int nt = 0; nt < 8; nt++) {
        int ch = cw * 32 + nt * 4 + t4;  // uint32 index = c/2
        __nv_bfloat162 p0 = __float22bfloat162_rn(make_float2(acc[nt][0], acc[nt][1]));
        __nv_bfloat162 p1 = __float22bfloat162_rn(make_float2(acc[nt][2], acc[nt][3]));
        mx[rowA * 260 + ch] = *(uint32_t*)&p0;
        mx[(rowA + 8) * 260 + ch] = *(uint32_t*)&p1;
    }
    __syncthreads();

    // residual + LN over c; warp handles 2 rows, v kept in registers
    const float alpha = *alpha_p;
#pragma unroll
    for (int rr = 0; rr < 2; rr++) {
        int li = wid * 2 + rr;
        float bul = bu[l0 + li];
        size_t xbase = ((size_t)b * L_ + l0 + li) * C_;
        float vx[16];
        float s = 0.f, ss = 0.f;
#pragma unroll
        for (int k = 0; k < 8; k++) {
            int j = lane + 32 * k;  // uint32 index; covers c = 2j, 2j+1
            uint32_t pm = mx[li * 260 + j];
            float2 m = __bfloat1622float2(*(__nv_bfloat162*)&pm);
            float2 xv = *(const float2*)&x[xbase + 2 * j];
            float v0 = xv.x + alpha * (m.x + bul);
            float v1 = xv.y + alpha * (m.y + bul);
            vx[2 * k] = v0;
            vx[2 * k + 1] = v1;
            s += v0 + v1;
            ss += v0 * v0 + v1 * v1;
        }
#pragma unroll
        for (int off = 16; off > 0; off >>= 1) {
            s += __shfl_xor_sync(0xffffffffu, s, off);
            ss += __shfl_xor_sync(0xffffffffu, ss, off);
        }
        float mu = s * (1.f / 512.f);
        float var = ss * (1.f / 512.f) - mu * mu;
        float rstd = rsqrtf(var + 1e-5f);
#pragma unroll
        for (int k = 0; k < 8; k++) {
            int j = lane + 32 * k;
            float2 gm = *(const float2*)&gamma[2 * j];
            float2 bt = *(const float2*)&beta[2 * j];
            float2 o;
            o.x = (vx[2 * k] - mu) * rstd * gm.x + bt.x;
            o.y = (vx[2 * k + 1] - mu) * rstd * gm.y + bt.y;
            *(float2*)&out[xbase + 2 * j] = o;
        }
    }
}

// ---------------------------------------------------------------------------
extern "C" void kernel_launch(void* const* d_in, const int* in_sizes, int n_in,
                              void* d_out, int out_size) {
    const float* x     = (const float*)d_in[0];
    const float* Wd    = (const float*)d_in[1];
    const float* bd    = (const float*)d_in[2];
    const float* Wq    = (const float*)d_in[3];
    const float* Wk    = (const float*)d_in[4];
    const float* Wv    = (const float*)d_in[5];
    const float* Wg    = (const float*)d_in[6];
    const float* bg    = (const float*)d_in[7];
    const float* Wu    = (const float*)d_in[8];
    const float* bu    = (const float*)d_in[9];
    const float* gamma = (const float*)d_in[10];
    const float* beta  = (const float*)d_in[11];
    const float* alpha = (const float*)d_in[12];
    float* out = (float*)d_out;

    static const int smem3 = (32 * 36 + 512 * 36) * 4;  // 78336 B
    static bool attr_set = false;
    if (!attr_set) {
        cudaFuncSetAttribute(k_out, cudaFuncAttributeMaxDynamicSharedMemorySize, smem3);
        attr_set = true;
    }

    k_hlow<<<dim3(8, B_, 2), 256>>>(x, Wd, bd);
    k_kv<<<dim3(8, B_), 256>>>(Wk, Wv);
    k_qg<<<dim3(8, B_), 256>>>(Wq, Wg, bg);
    k_out<<<dim3(64, B_), 512, smem3>>>(x, Wu, bu, gamma, beta, alpha, out);
}